// round 5
// baseline (speedup 1.0000x reference)
#include <cuda_runtime.h>
#include <cuda_fp16.h>
#include <cstdint>

// Shapes fixed by dataset: B=64, E=16, D=64, Q_DIM=64 -> K=128.
#define B_DIM    64
#define K_DIM    128
#define NTILE    64
#define THREADS  256
#define HIST_CAP 262144
#define PITCH    136           // halves per row in fp16 tile buffers

// SMEM layout (bytes)
#define OFF_XL    0            // 64 x 136 halves = 17408 (X lo, permanent)
#define OFF_AH    17408        // A hi fp16 tile
#define OFF_AL    34816        // A lo fp16 tile
#define OFF_STAGE 52224        // 64 x 128 fp32 = 32768 (cp.async stage / XH temp)
#define OFF_STG   84992        // 64 x 68 fp32 = 17408 (output staging)
#define OFF_COLS  102400       // 2 x 64 ints (double-buffered)
#define SMEM_TOTAL 102912

__device__ __half g_Xh[B_DIM * K_DIM];
__device__ __half g_Xl[B_DIM * K_DIM];
__device__ float  g_hist[HIST_CAP];

// ---------------------------------------------------------------------------
__device__ __forceinline__ uint32_t smem_u32(const void* p) {
    uint32_t a;
    asm("{ .reg .u64 t; cvta.to.shared.u64 t, %1; cvt.u32.u64 %0, t; }"
        : "=r"(a) : "l"(p));
    return a;
}

__device__ __forceinline__ uint32_t packh(float lo, float hi) {
    uint32_t r;
    asm("cvt.rn.f16x2.f32 %0, %1, %2;" : "=r"(r) : "f"(hi), "f"(lo));
    return r;
}

__device__ __forceinline__ void mma16816(float* d, const uint32_t* a,
                                         uint32_t b0, uint32_t b1) {
    asm volatile(
        "mma.sync.aligned.m16n8k16.row.col.f32.f16.f16.f32 "
        "{%0,%1,%2,%3}, {%4,%5,%6,%7}, {%8,%9}, {%0,%1,%2,%3};"
        : "+f"(d[0]), "+f"(d[1]), "+f"(d[2]), "+f"(d[3])
        : "r"(a[0]), "r"(a[1]), "r"(a[2]), "r"(a[3]), "r"(b0), "r"(b1));
}

__device__ __forceinline__ void ldsm4(uint32_t* r, uint32_t addr) {
    asm volatile("ldmatrix.sync.aligned.m8n8.x4.shared.b16 {%0,%1,%2,%3}, [%4];"
                 : "=r"(r[0]), "=r"(r[1]), "=r"(r[2]), "=r"(r[3]) : "r"(addr));
}

__device__ __forceinline__ void cpasync_tile(uint32_t stage,
                                             const float* __restrict__ W,
                                             const float* __restrict__ U,
                                             int n0, int n_np, int tid) {
#pragma unroll
    for (int j = 0; j < 8; ++j) {
        int chunk = tid + THREADS * j;       // 0..2047 (16B chunks)
        int row = chunk >> 5, kc = (chunk & 31) << 2;
        int n = n0 + row;
        const float* src = (kc < 64) ? (W + (size_t)n * 64 + kc)
                                     : (U + (size_t)n * 64 + (kc - 64));
        if (n < n_np)
            asm volatile("cp.async.cg.shared.global [%0], [%1], 16;"
                         :: "r"(stage + row * 512 + kc * 4), "l"(src));
    }
    asm volatile("cp.async.commit_group;" ::: "memory");
}

// ---------------------------------------------------------------------------
// Persistent HMMA GEMM, 2 CTAs/SM. B(X)-hi fragments hoisted to registers.
__global__ __launch_bounds__(THREADS, 2)
void gemm_kernel(const float* __restrict__ W, const float* __restrict__ U,
                 const int* __restrict__ npi, float* __restrict__ V,
                 int n_np, int n_atoms, int n_tiles) {
    extern __shared__ char smem[];
    const uint32_t sb = smem_u32(smem);
    const int tid = threadIdx.x;
    const int wid = tid >> 5, lane = tid & 31;
    const int bg = wid >> 2;                 // b-group: 0 -> b 0-31, 1 -> 32-63
    const int m0 = (wid & 3) * 16;           // warp's W-row base
    const int qr = lane >> 2, qc = lane & 3;
    const int r0 = m0 + qr, r1 = r0 + 8;

    // prologue: X-hi -> stage (temp), X-lo -> XL (permanent); pitch-136 halves
    for (int idx = tid; idx < 4096; idx += THREADS) {
        int b = idx >> 6, kp = (idx & 63) * 2;
        uint32_t d = (b * PITCH + kp) * 2;
        *(uint32_t*)(smem + OFF_STAGE + d) = ((const uint32_t*)g_Xh)[idx];
        *(uint32_t*)(smem + OFF_XL + d)    = ((const uint32_t*)g_Xl)[idx];
    }
    __syncthreads();

    // hoist B-hi fragments: 8 ks x 2 nb x 4 regs
    const int xrow = bg * 32 + (lane & 7) + ((lane >> 4) << 3);
    const int xcol = ((lane >> 3) & 1) << 3;
    uint32_t bhr[64];
#pragma unroll
    for (int ks = 0; ks < 8; ++ks)
#pragma unroll
        for (int nb = 0; nb < 2; ++nb)
            ldsm4(&bhr[(ks * 2 + nb) * 4],
                  sb + OFF_STAGE + ((xrow + nb * 16) * PITCH + ks * 16 + xcol) * 2);
    __syncthreads();                          // stage free for cp.async

    // A-fragment lane addressing
    const int arow = (lane & 7) + (((lane >> 3) & 1) << 3);
    const int acol = (lane >> 4) << 3;
    const uint32_t Aoff = ((m0 + arow) * PITCH + acol) * 2;

    const int bid = blockIdx.x, grid = gridDim.x;
    const int ntl = (n_tiles > bid) ? ((n_tiles - 1 - bid) / grid + 1) : 0;
    if (ntl) cpasync_tile(sb + OFF_STAGE, W, U, bid * NTILE, n_np, tid);

    const int bcol_store = tid & 63;          // store-phase b index
    const int qrow_store = tid >> 6;          // store-phase row quad group

    for (int i = 0; i < ntl; ++i) {
        asm volatile("cp.async.wait_group 0;" ::: "memory");
        const int n0 = (bid + i * grid) * NTILE;
        int* cols = (int*)(smem + OFF_COLS + (i & 1) * 256);
        if (tid < 64) {
            int n = n0 + tid;
            cols[tid] = (n < n_np) ? npi[n] : npi[n_np - 1];
        }

        // cvt: fp32 stage -> fp16 hi/lo tiles
#pragma unroll
        for (int j = 0; j < 8; ++j) {
            int chunk = tid + THREADS * j;
            int row = chunk >> 5, kc = (chunk & 31) << 2;
            float4 v = *(const float4*)(smem + OFF_STAGE + row * 512 + kc * 4);
            uint32_t h01 = packh(v.x, v.y), h23 = packh(v.z, v.w);
            __half2 H01 = *(__half2*)&h01, H23 = *(__half2*)&h23;
            uint32_t l01 = packh(v.x - __low2float(H01), v.y - __high2float(H01));
            uint32_t l23 = packh(v.z - __low2float(H23), v.w - __high2float(H23));
            uint32_t d = sb + OFF_AH + (row * PITCH + kc) * 2;
            asm volatile("st.shared.v2.b32 [%0], {%1,%2};" :: "r"(d), "r"(h01), "r"(h23));
            asm volatile("st.shared.v2.b32 [%0], {%1,%2};"
                         :: "r"(d + (OFF_AL - OFF_AH)), "r"(l01), "r"(l23));
        }
        __syncthreads();                      // A tiles + cols visible; stage consumed

        if (i + 1 < ntl)
            cpasync_tile(sb + OFF_STAGE, W, U, (bid + (i + 1) * grid) * NTILE,
                         n_np, tid);

        const float hv0 = g_hist[cols[r0]];
        const float hv1 = g_hist[cols[r1]];

        float d[4][4] = {};
#pragma unroll
        for (int ks = 0; ks < 8; ++ks) {
            uint32_t ah[4], al[4];
            ldsm4(ah, sb + OFF_AH + Aoff + ks * 32);
            ldsm4(al, sb + OFF_AL + Aoff + ks * 32);
#pragma unroll
            for (int nb = 0; nb < 2; ++nb) {
                uint32_t bl[4];
                ldsm4(bl, sb + OFF_XL + ((xrow + nb * 16) * PITCH + ks * 16 + xcol) * 2);
                const uint32_t* bh = &bhr[(ks * 2 + nb) * 4];
                mma16816(d[2 * nb],     ah, bh[0], bh[1]);
                mma16816(d[2 * nb],     al, bh[0], bh[1]);
                mma16816(d[2 * nb],     ah, bl[0], bl[1]);
                mma16816(d[2 * nb + 1], ah, bh[2], bh[3]);
                mma16816(d[2 * nb + 1], al, bh[2], bh[3]);
                mma16816(d[2 * nb + 1], ah, bl[2], bl[3]);
            }
        }

        // epilogue: sigmoid(s) = 0.5 + 0.5*tanh(s/2) + hist -> staged[row][bcol]
        float* stg = (float*)(smem + OFF_STG);
#pragma unroll
        for (int q = 0; q < 4; ++q) {
#pragma unroll
            for (int h = 0; h < 2; ++h) {
                float t0, t1;
                asm("tanh.approx.f32 %0, %1;" : "=f"(t0) : "f"(0.5f * d[q][2 * h]));
                asm("tanh.approx.f32 %0, %1;" : "=f"(t1) : "f"(0.5f * d[q][2 * h + 1]));
                float base = 0.5f + (h ? hv1 : hv0);
                float v0 = fmaf(0.5f, t0, base);
                float v1 = fmaf(0.5f, t1, base);
                int row = h ? r1 : r0;
                int bc  = bg * 32 + q * 8 + 2 * qc;
                uint32_t dsta = sb + OFF_STG + (row * 68 + bc) * 4;
                asm volatile("st.shared.v2.b32 [%0], {%1,%2};"
                             :: "r"(dsta), "r"(__float_as_uint(v0)),
                                "r"(__float_as_uint(v1)));
            }
        }
        __syncthreads();                      // staged visible; all A/X ldsm done

        // store phase: thread -> (b = tid&63), 4 quads of 4 consecutive rows
#pragma unroll
        for (int w = 0; w < 4; ++w) {
            int nnq = qrow_store * 16 + w * 4;
            float o0 = stg[(nnq + 0) * 68 + bcol_store];
            float o1 = stg[(nnq + 1) * 68 + bcol_store];
            float o2 = stg[(nnq + 2) * 68 + bcol_store];
            float o3 = stg[(nnq + 3) * 68 + bcol_store];
            int c0 = cols[nnq], c1 = cols[nnq + 1];
            int c2 = cols[nnq + 2], c3 = cols[nnq + 3];
            float* dst = V + (size_t)bcol_store * n_atoms + c0;
            bool fast = (c1 == c0 + 1) && (c2 == c0 + 2) && (c3 == c0 + 3) &&
                        ((c0 & 3) == 0) && (n0 + nnq + 3 < n_np);
            if (fast) {
                *(float4*)dst = make_float4(o0, o1, o2, o3);
            } else {
                if (n0 + nnq     < n_np) V[(size_t)bcol_store * n_atoms + c0] = o0;
                if (n0 + nnq + 1 < n_np) V[(size_t)bcol_store * n_atoms + c1] = o1;
                if (n0 + nnq + 2 < n_np) V[(size_t)bcol_store * n_atoms + c2] = o2;
                if (n0 + nnq + 3 < n_np) V[(size_t)bcol_store * n_atoms + c3] = o3;
            }
        }
        // no extra sync: next iter's first write to stg comes after its own barrier
    }
}

// ---------------------------------------------------------------------------
// prep: X = [sum_e Z | Q] split to fp16 hi/lo; zero hist.
__global__ void prep_kernel(const float* __restrict__ Z, const float* __restrict__ Q,
                            int n_atoms) {
    if (blockIdx.x < B_DIM) {
        int b = blockIdx.x, k = threadIdx.x;
        if (k < K_DIM) {
            float s;
            if (k < 64) {
                s = 0.f;
#pragma unroll
                for (int e = 0; e < 16; ++e) s += Z[(b * 16 + e) * 64 + k];
            } else {
                s = Q[b * 64 + (k - 64)];
            }
            __half h = __float2half_rn(s);
            g_Xh[b * K_DIM + k] = h;
            g_Xl[b * K_DIM + k] = __float2half_rn(s - __half2float(h));
        }
    } else {
        int idx = (blockIdx.x - B_DIM) * blockDim.x + threadIdx.x;
        int n4 = (n_atoms + 3) >> 2;
        if (idx < n4) ((float4*)g_hist)[idx] = make_float4(0.f, 0.f, 0.f, 0.f);
    }
}

__global__ void hist_kernel(const int* __restrict__ bk, int n_bk) {
    int i = blockIdx.x * blockDim.x + threadIdx.x;
    if (i < n_bk) atomicAdd(&g_hist[bk[i]], 1.0f);
}

// tail: V[b][c] = hist[c] for c in [n_np, n_atoms); V[b][0] = 1 + hist[0]
// (gemm launches after on the same stream and overwrites col 0 via npi — matches ref)
__global__ void tail_kernel(float* __restrict__ V, int n_np, int n_atoms) {
    int b = blockIdx.y;
    int per4 = (n_atoms - n_np) >> 2;
    int idx = blockIdx.x * blockDim.x + threadIdx.x;
    if (idx < per4) {
        float4 h = ((const float4*)(g_hist + n_np))[idx];
        ((float4*)(V + (size_t)b * n_atoms + n_np))[idx] = h;
    }
    if (blockIdx.x == 0 && threadIdx.x == 0)
        V[(size_t)b * n_atoms] = 1.0f + g_hist[0];
}

// ---------------------------------------------------------------------------
extern "C" void kernel_launch(void* const* d_in, const int* in_sizes, int n_in,
                              void* d_out, int out_size) {
    const float* Z   = (const float*)d_in[0];
    const float* Q   = (const float*)d_in[1];
    const float* W   = (const float*)d_in[2];
    const float* U   = (const float*)d_in[3];
    const int*   npi = (const int*)d_in[4];
    const int*   bk  = (const int*)d_in[5];
    const int n_np    = in_sizes[4];
    const int n_bk    = in_sizes[5];
    const int n_atoms = out_size / B_DIM;
    float* V = (float*)d_out;

    int nsm = 0;
    cudaDeviceGetAttribute(&nsm, cudaDevAttrMultiProcessorCount, 0);
    if (nsm <= 0) nsm = 148;
    cudaFuncSetAttribute(gemm_kernel,
                         cudaFuncAttributeMaxDynamicSharedMemorySize, SMEM_TOTAL);

    int n_tiles = (n_np + NTILE - 1) / NTILE;
    int zb = ((n_atoms + 3) / 4 + 127) / 128;
    prep_kernel<<<B_DIM + zb, 128>>>(Z, Q, n_atoms);
    hist_kernel<<<(n_bk + 255) / 256, 256>>>(bk, n_bk);
    int per4 = (n_atoms - n_np) >> 2;
    dim3 tg((per4 + 255) / 256, B_DIM);
    tail_kernel<<<tg, 256>>>(V, n_np, n_atoms);
    int g = 2 * nsm < n_tiles ? 2 * nsm : n_tiles;
    gemm_kernel<<<g, THREADS, SMEM_TOTAL>>>(W, U, npi, V, n_np, n_atoms, n_tiles);
}

// round 6
// speedup vs baseline: 1.1464x; 1.1464x over previous
#include <cuda_runtime.h>
#include <cuda_fp16.h>
#include <cstdint>

// Shapes fixed by dataset: B=64, E=16, D=64, Q_DIM=64 -> K=128.
#define B_DIM    64
#define K_DIM    128
#define NTILE    64
#define THREADS  256
#define HIST_CAP 262144
#define PITCH    136           // halves per row (272B): ldsm conflict-free
#define ABUF     34816         // Ah+Al per buffer (2 x 17408)
#define AL_DELTA 17408

// SMEM layout (bytes)
#define OFF_XH   0             // 64 x 136 halves = 17408
#define OFF_XL   17408
#define OFF_A    34816         // [Ah0, Al0, Ah1, Al1] = 4 x 17408 = 69632
#define OFF_COLS 104448        // 2 x 64 ints
#define SMEM_TOTAL 104960
// staged output (64 x 66 fp32 = 16896B) aliases Ah[(i+1)&1]

__device__ __half g_Xh[B_DIM * K_DIM];
__device__ __half g_Xl[B_DIM * K_DIM];
__device__ float  g_hist[HIST_CAP];

// ---------------------------------------------------------------------------
__device__ __forceinline__ uint32_t smem_u32(const void* p) {
    uint32_t a;
    asm("{ .reg .u64 t; cvta.to.shared.u64 t, %1; cvt.u32.u64 %0, t; }"
        : "=r"(a) : "l"(p));
    return a;
}

__device__ __forceinline__ uint32_t packh(float lo, float hi) {
    uint32_t r;
    asm("cvt.rn.f16x2.f32 %0, %1, %2;" : "=r"(r) : "f"(hi), "f"(lo));
    return r;
}

__device__ __forceinline__ void mma16816(float* d, const uint32_t* a,
                                         uint32_t b0, uint32_t b1) {
    asm volatile(
        "mma.sync.aligned.m16n8k16.row.col.f32.f16.f16.f32 "
        "{%0,%1,%2,%3}, {%4,%5,%6,%7}, {%8,%9}, {%0,%1,%2,%3};"
        : "+f"(d[0]), "+f"(d[1]), "+f"(d[2]), "+f"(d[3])
        : "r"(a[0]), "r"(a[1]), "r"(a[2]), "r"(a[3]), "r"(b0), "r"(b1));
}

__device__ __forceinline__ void ldsm4(uint32_t* r, uint32_t addr) {
    asm volatile("ldmatrix.sync.aligned.m8n8.x4.shared.b16 {%0,%1,%2,%3}, [%4];"
                 : "=r"(r[0]), "=r"(r[1]), "=r"(r[2]), "=r"(r[3]) : "r"(addr));
}

__device__ __forceinline__ void ldg_tile(float4* pf, const float* __restrict__ W,
                                         const float* __restrict__ U,
                                         int n0, int n_np, int tid) {
#pragma unroll
    for (int j = 0; j < 8; ++j) {
        int chunk = tid + THREADS * j;        // 0..2047 (16B chunks)
        int row = chunk >> 5, kc = (chunk & 31) << 2;
        int n = n0 + row;
        const float* src = (kc < 64) ? (W + (size_t)n * 64 + kc)
                                     : (U + (size_t)n * 64 + (kc - 64));
        if (n < n_np) pf[j] = *(const float4*)src;
    }
}

__device__ __forceinline__ void cvt_sts(const float4* pf, uint32_t ah_base, int tid) {
#pragma unroll
    for (int j = 0; j < 8; ++j) {
        int chunk = tid + THREADS * j;
        int row = chunk >> 5, kc = (chunk & 31) << 2;
        float4 v = pf[j];
        uint32_t h01 = packh(v.x, v.y), h23 = packh(v.z, v.w);
        __half2 H01 = *(__half2*)&h01, H23 = *(__half2*)&h23;
        uint32_t l01 = packh(v.x - __low2float(H01), v.y - __high2float(H01));
        uint32_t l23 = packh(v.z - __low2float(H23), v.w - __high2float(H23));
        uint32_t d = ah_base + (row * PITCH + kc) * 2;
        asm volatile("st.shared.v2.b32 [%0], {%1,%2};" :: "r"(d), "r"(h01), "r"(h23));
        asm volatile("st.shared.v2.b32 [%0], {%1,%2};"
                     :: "r"(d + AL_DELTA), "r"(l01), "r"(l23));
    }
}

// ---------------------------------------------------------------------------
// Persistent HMMA GEMM, 2 CTAs/SM, 3 syncs/tile, staging aliased on idle A buf.
__global__ __launch_bounds__(THREADS, 2)
void gemm_kernel(const float* __restrict__ W, const float* __restrict__ U,
                 const int* __restrict__ npi, float* __restrict__ V,
                 int n_np, int n_atoms, int n_tiles) {
    extern __shared__ char smem[];
    const uint32_t sb = smem_u32(smem);
    const int tid = threadIdx.x;
    const int wid = tid >> 5, lane = tid & 31;
    const int bg = wid >> 2;                 // b-group: 0 -> b 0-31, 1 -> 32-63
    const int m0 = (wid & 3) * 16;           // warp's W-row base
    const int qr = lane >> 2, qc = lane & 3;
    const int r0 = m0 + qr, r1 = r0 + 8;
    int* colsA = (int*)(smem + OFF_COLS);    // [2][64]

    // prologue: X (hi/lo) -> smem
    for (int idx = tid; idx < 4096; idx += THREADS) {
        int b = idx >> 6, kp = (idx & 63) * 2;
        uint32_t d = (b * PITCH + kp) * 2;
        *(uint32_t*)(smem + OFF_XH + d) = ((const uint32_t*)g_Xh)[idx];
        *(uint32_t*)(smem + OFF_XL + d)  = ((const uint32_t*)g_Xl)[idx];
    }

    const int bid = blockIdx.x, grid = gridDim.x;
    const int ntl = (n_tiles > bid) ? ((n_tiles - 1 - bid) / grid + 1) : 0;

    if (tid < 64 && ntl) {                   // cols for tile 0
        int n = bid * NTILE + tid;
        colsA[tid] = (n < n_np) ? npi[n] : npi[n_np - 1];
    }
    // V[:,0] = 1 + hist[0]; CTA0's own later store to col 0 is sync-ordered
    if (bid == 0 && tid < B_DIM)
        V[(size_t)tid * n_atoms] = 1.0f + g_hist[0];

    float4 pf[8];
    if (ntl) {
        ldg_tile(pf, W, U, bid * NTILE, n_np, tid);
        cvt_sts(pf, sb + OFF_A, tid);        // buffer 0
    }

    // fragment lane addressing
    const int arow = (lane & 7) + (((lane >> 3) & 1) << 3);
    const int acol = (lane >> 4) << 3;
    const uint32_t Aoff = ((m0 + arow) * PITCH + acol) * 2;
    const int xrow = bg * 32 + (lane & 7) + ((lane >> 4) << 3);
    const int xcol = ((lane >> 3) & 1) << 3;

    for (int i = 0; i < ntl; ++i) {
        const int cur = i & 1, nxt = cur ^ 1;
        const int n0 = (bid + i * grid) * NTILE;
        __syncthreads();                     // S1: A buf cur + cols[cur] visible

        if (i + 1 < ntl) {
            ldg_tile(pf, W, U, (bid + (i + 1) * grid) * NTILE, n_np, tid);
            if (tid < 64) {
                int n = (bid + (i + 1) * grid) * NTILE + tid;
                colsA[nxt * 64 + tid] = (n < n_np) ? npi[n] : npi[n_np - 1];
            }
        }
        const int* cols = colsA + cur * 64;
        const float hv0 = g_hist[cols[r0]];
        const float hv1 = g_hist[cols[r1]];

        const uint32_t AH = sb + OFF_A + cur * ABUF + Aoff;
        float d[4][4] = {};
#pragma unroll
        for (int ks = 0; ks < 8; ++ks) {
            uint32_t ah[4], al[4];
            ldsm4(ah, AH + ks * 32);
            ldsm4(al, AH + AL_DELTA + ks * 32);
#pragma unroll
            for (int nb = 0; nb < 2; ++nb) {
                uint32_t bh[4], bl[4];
                uint32_t xoff = ((xrow + nb * 16) * PITCH + ks * 16 + xcol) * 2;
                ldsm4(bh, sb + OFF_XH + xoff);
                ldsm4(bl, sb + OFF_XL + xoff);
                mma16816(d[2 * nb],     ah, bh[0], bh[1]);
                mma16816(d[2 * nb],     al, bh[0], bh[1]);
                mma16816(d[2 * nb],     ah, bl[0], bl[1]);
                mma16816(d[2 * nb + 1], ah, bh[2], bh[3]);
                mma16816(d[2 * nb + 1], al, bh[2], bh[3]);
                mma16816(d[2 * nb + 1], ah, bl[2], bl[3]);
            }
        }

        // epilogue: sigmoid + hist -> staged[b][n], aliased on Ah[nxt]
        const uint32_t stg_u = sb + OFF_A + nxt * ABUF;
#pragma unroll
        for (int q = 0; q < 4; ++q) {
#pragma unroll
            for (int j = 0; j < 4; ++j) {
                float t;
                asm("tanh.approx.f32 %0, %1;" : "=f"(t) : "f"(0.5f * d[q][j]));
                float v = fmaf(0.5f, t, 0.5f + ((j >> 1) ? hv1 : hv0));
                int bcol = bg * 32 + q * 8 + 2 * qc + (j & 1);
                int nrow = r0 + ((j >> 1) << 3);
                asm volatile("st.shared.b32 [%0], %1;"
                             :: "r"(stg_u + (bcol * 66 + nrow) * 4),
                                "r"(__float_as_uint(v)));
            }
        }
        __syncthreads();                     // S2: staged visible, all ldsm done

        // store: warp writes 32 consecutive n of one b-row (coalesced)
        const float* stg = (const float*)(smem + OFF_A + nxt * ABUF);
#pragma unroll
        for (int e = 0; e < 16; ++e) {
            int el = tid + THREADS * e;      // 0..4095
            int bb = el >> 6, nn = el & 63;
            if (n0 + nn < n_np)
                V[(size_t)bb * n_atoms + cols[nn]] = stg[bb * 66 + nn];
        }
        __syncthreads();                     // S3: store done before cvt clobbers

        if (i + 1 < ntl)
            cvt_sts(pf, sb + OFF_A + nxt * ABUF, tid);
    }

    // fused tail: V[b][c] = hist[c] for c in [n_np, n_atoms), grid-strided
    const int total4 = (n_atoms - n_np) >> 2;
    const float4* h4 = (const float4*)(g_hist + n_np);
    for (int t = bid * THREADS + tid; t < B_DIM * total4; t += grid * THREADS) {
        int b = t / total4, c4 = t - b * total4;
        ((float4*)(V + (size_t)b * n_atoms + n_np))[c4] = h4[c4];
    }
}

// ---------------------------------------------------------------------------
// prep: X = [sum_e Z | Q] split to fp16 hi/lo; zero hist.
__global__ void prep_kernel(const float* __restrict__ Z, const float* __restrict__ Q,
                            int n_atoms) {
    if (blockIdx.x < B_DIM) {
        int b = blockIdx.x, k = threadIdx.x;
        if (k < K_DIM) {
            float s;
            if (k < 64) {
                s = 0.f;
#pragma unroll
                for (int e = 0; e < 16; ++e) s += Z[(b * 16 + e) * 64 + k];
            } else {
                s = Q[b * 64 + (k - 64)];
            }
            __half h = __float2half_rn(s);
            g_Xh[b * K_DIM + k] = h;
            g_Xl[b * K_DIM + k] = __float2half_rn(s - __half2float(h));
        }
    } else {
        int idx = (blockIdx.x - B_DIM) * blockDim.x + threadIdx.x;
        int n4 = (n_atoms + 3) >> 2;
        if (idx < n4) ((float4*)g_hist)[idx] = make_float4(0.f, 0.f, 0.f, 0.f);
    }
}

__global__ void hist_kernel(const int* __restrict__ bk, int n_bk) {
    int i = blockIdx.x * blockDim.x + threadIdx.x;
    if (i < n_bk) atomicAdd(&g_hist[bk[i]], 1.0f);
}

// ---------------------------------------------------------------------------
extern "C" void kernel_launch(void* const* d_in, const int* in_sizes, int n_in,
                              void* d_out, int out_size) {
    const float* Z   = (const float*)d_in[0];
    const float* Q   = (const float*)d_in[1];
    const float* W   = (const float*)d_in[2];
    const float* U   = (const float*)d_in[3];
    const int*   npi = (const int*)d_in[4];
    const int*   bk  = (const int*)d_in[5];
    const int n_np    = in_sizes[4];
    const int n_bk    = in_sizes[5];
    const int n_atoms = out_size / B_DIM;
    float* V = (float*)d_out;

    int nsm = 0;
    cudaDeviceGetAttribute(&nsm, cudaDevAttrMultiProcessorCount, 0);
    if (nsm <= 0) nsm = 148;
    cudaFuncSetAttribute(gemm_kernel,
                         cudaFuncAttributeMaxDynamicSharedMemorySize, SMEM_TOTAL);

    int n_tiles = (n_np + NTILE - 1) / NTILE;
    int zb = ((n_atoms + 3) / 4 + 127) / 128;
    prep_kernel<<<B_DIM + zb, 128>>>(Z, Q, n_atoms);
    hist_kernel<<<(n_bk + 255) / 256, 256>>>(bk, n_bk);
    int g = 2 * nsm < n_tiles ? 2 * nsm : n_tiles;
    gemm_kernel<<<g, THREADS, SMEM_TOTAL>>>(W, U, npi, V, n_np, n_atoms, n_tiles);
}